// round 14
// baseline (speedup 1.0000x reference)
#include <cuda_runtime.h>
#include <math.h>

#define N_NODES  200000
#define N_HEDGES 100000
#define N_INC    1600000
#define D        64
#define N_SEG    (N_NODES + N_HEDGES)       // 300000
#define SCAN_BLOCKS 74                       // ceil(300000 / 4096)

// ---------------- scratch (static device globals; no allocation) ------------
__device__ float g_hedge_proj[N_HEDGES * D];   // hedge_features @ W_nh
__device__ float g_node_proj [N_NODES  * D];   // new_node @ W_hn
__device__ float g_gate_node [N_NODES  * D];   // segment_sum -> nodes
__device__ int   g_hist[N_SEG];                // counts, then reused as cursors
__device__ int   g_off [N_SEG + 1];            // CSR offsets (combined node|hedge)
__device__ int   g_blocksums[128];
__device__ int   g_ord[2 * N_INC];             // CSR adjacency (source row ids)

// ---------------- helpers ----------------------------------------------------
__device__ __forceinline__ unsigned tf_hi(float f) {
    unsigned r;
    asm("cvt.rna.tf32.f32 %0, %1;" : "=r"(r) : "f"(f));
    return r;
}

__device__ __forceinline__ void mma_tf32(float* c,
                                         unsigned a0, unsigned a1, unsigned a2, unsigned a3,
                                         unsigned b0, unsigned b1)
{
    asm volatile(
        "mma.sync.aligned.m16n8k8.row.col.f32.tf32.tf32.f32 "
        "{%0,%1,%2,%3}, {%4,%5,%6,%7}, {%8,%9}, {%0,%1,%2,%3};"
        : "+f"(c[0]), "+f"(c[1]), "+f"(c[2]), "+f"(c[3])
        : "r"(a0), "r"(a1), "r"(a2), "r"(a3), "r"(b0), "r"(b1));
}

// Build B fragments in MMA fragment order from global W (16 KB, L2-hot).
__device__ __forceinline__ void build_bfrag(const float* __restrict__ W, float4* Bfrag, int t)
{
    const int lane = t & 31;
    const int kk   = t >> 5;               // 0..7
    const int grp  = lane >> 2;
    const int tig  = lane & 3;
    const int base = (kk * 8 + tig) * 64 + grp;
    #pragma unroll
    for (int nt = 0; nt < 8; nt++) {
        float v0 = __ldg(&W[base + nt * 8]);
        float v1 = __ldg(&W[base + 4 * 64 + nt * 8]);
        float h0 = __uint_as_float(tf_hi(v0));
        float h1 = __uint_as_float(tf_hi(v1));
        float l0 = __uint_as_float(tf_hi(v0 - h0));
        float l1 = __uint_as_float(tf_hi(v1 - h1));
        Bfrag[(nt * 8 + kk) * 32 + lane] = make_float4(h0, h1, l0, l1);
    }
}

// 3xTF32 mainloop: acc[2][4][4] over 32x32 warp tile. A from Xs (stride 68),
// B from fragment-packed smem.
__device__ __forceinline__ void mma_mainloop(const float* __restrict__ Xs,
                                             const float4* __restrict__ Bfrag,
                                             float acc[2][4][4],
                                             int mw, int nw, int grp, int tig, int lane)
{
    #pragma unroll
    for (int mt = 0; mt < 2; mt++)
        #pragma unroll
        for (int nt = 0; nt < 4; nt++)
            #pragma unroll
            for (int j = 0; j < 4; j++) acc[mt][nt][j] = 0.f;

    const float* xr00 = &Xs[(mw * 32 +      grp) * 68];
    const float* xr01 = &Xs[(mw * 32 +  8 + grp) * 68];
    const float* xr10 = &Xs[(mw * 32 + 16 + grp) * 68];
    const float* xr11 = &Xs[(mw * 32 + 24 + grp) * 68];

    #pragma unroll
    for (int kk = 0; kk < 8; kk++) {
        const int kb = kk * 8;
        unsigned ah[2][4], al[2][4];
        {
            float x0, x1, x2, x3;
            x0 = xr00[kb + tig]; x1 = xr01[kb + tig];
            x2 = xr00[kb + tig + 4]; x3 = xr01[kb + tig + 4];
            ah[0][0] = tf_hi(x0); al[0][0] = tf_hi(x0 - __uint_as_float(ah[0][0]));
            ah[0][1] = tf_hi(x1); al[0][1] = tf_hi(x1 - __uint_as_float(ah[0][1]));
            ah[0][2] = tf_hi(x2); al[0][2] = tf_hi(x2 - __uint_as_float(ah[0][2]));
            ah[0][3] = tf_hi(x3); al[0][3] = tf_hi(x3 - __uint_as_float(ah[0][3]));
            x0 = xr10[kb + tig]; x1 = xr11[kb + tig];
            x2 = xr10[kb + tig + 4]; x3 = xr11[kb + tig + 4];
            ah[1][0] = tf_hi(x0); al[1][0] = tf_hi(x0 - __uint_as_float(ah[1][0]));
            ah[1][1] = tf_hi(x1); al[1][1] = tf_hi(x1 - __uint_as_float(ah[1][1]));
            ah[1][2] = tf_hi(x2); al[1][2] = tf_hi(x2 - __uint_as_float(ah[1][2]));
            ah[1][3] = tf_hi(x3); al[1][3] = tf_hi(x3 - __uint_as_float(ah[1][3]));
        }
        #pragma unroll
        for (int nt = 0; nt < 4; nt++) {
            float4 b = Bfrag[((nw * 4 + nt) * 8 + kk) * 32 + lane];
            unsigned bh0 = __float_as_uint(b.x);
            unsigned bh1 = __float_as_uint(b.y);
            unsigned bl0 = __float_as_uint(b.z);
            unsigned bl1 = __float_as_uint(b.w);
            #pragma unroll
            for (int mt = 0; mt < 2; mt++) {
                mma_tf32(acc[mt][nt], ah[mt][0], ah[mt][1], ah[mt][2], ah[mt][3], bh0, bh1);
                mma_tf32(acc[mt][nt], al[mt][0], al[mt][1], al[mt][2], al[mt][3], bh0, bh1);
                mma_tf32(acc[mt][nt], ah[mt][0], ah[mt][1], ah[mt][2], ah[mt][3], bl0, bl1);
            }
        }
    }
}

// stage a 128-row X tile (raw fp32) into Xs, stride 68, OOB rows -> 0
__device__ __forceinline__ void stage_x(const float* __restrict__ X, float* Xs,
                                        int row0, int M, int t)
{
    const float4* X4 = (const float4*)X;
    #pragma unroll
    for (int jj = 0; jj < 8; jj++) {
        int i4  = t + jj * 256;
        int r   = i4 >> 4;
        int kq  = i4 & 15;
        int row = row0 + r;
        float4 v = make_float4(0.f, 0.f, 0.f, 0.f);
        if (row < M) v = X4[row * 16 + kq];
        float* p = &Xs[r * 68 + kq * 4];
        p[0] = v.x; p[1] = v.y; p[2] = v.z; p[3] = v.w;
    }
}

// ---------------- plain GEMM kernel (step 1: hedge_proj) ---------------------
__global__ __launch_bounds__(256)
void proj_mma_kernel(const float* __restrict__ X, const float* __restrict__ W,
                     float* __restrict__ out, int M)
{
    __shared__ float  Xs[128 * 68];
    __shared__ float4 Bfrag[8 * 8 * 32];

    const int t    = threadIdx.x;
    const int row0 = blockIdx.x * 128;

    build_bfrag(W, Bfrag, t);
    stage_x(X, Xs, row0, M, t);
    __syncthreads();

    const int lane = t & 31;
    const int w    = t >> 5;
    const int mw   = w >> 1;
    const int nw   = w & 1;
    const int grp  = lane >> 2;
    const int tig  = lane & 3;

    float acc[2][4][4];
    mma_mainloop(Xs, Bfrag, acc, mw, nw, grp, tig, lane);

    #pragma unroll
    for (int mt = 0; mt < 2; mt++) {
        const int r0 = row0 + mw * 32 + mt * 16 + grp;
        const int r1 = r0 + 8;
        #pragma unroll
        for (int nt = 0; nt < 4; nt++) {
            const int c = nw * 32 + nt * 8 + tig * 2;
            if (r0 < M) *(float2*)&out[r0 * 64 + c] = make_float2(acc[mt][nt][0], acc[mt][nt][1]);
            if (r1 < M) *(float2*)&out[r1 * 64 + c] = make_float2(acc[mt][nt][2], acc[mt][nt][3]);
        }
    }
}

// ---------------- fused node kernel (steps 3+4) ------------------------------
// pass1: out_node = tanh((node_f @ W_nn) * gate)   (written to gmem AND Xs)
// pass2: node_proj = out_node @ W_hn
__global__ __launch_bounds__(256, 2)
void fused_node_kernel(const float* __restrict__ X, const float* __restrict__ Wnn,
                       const float* __restrict__ Whn, const float* __restrict__ gate,
                       float* __restrict__ out_node, float* __restrict__ node_proj, int M)
{
    __shared__ float  Xs[128 * 68];
    __shared__ float4 Bfrag0[8 * 8 * 32];
    __shared__ float4 Bfrag1[8 * 8 * 32];

    const int t    = threadIdx.x;
    const int row0 = blockIdx.x * 128;

    build_bfrag(Wnn, Bfrag0, t);
    build_bfrag(Whn, Bfrag1, t);
    stage_x(X, Xs, row0, M, t);
    __syncthreads();

    const int lane = t & 31;
    const int w    = t >> 5;
    const int mw   = w >> 1;
    const int nw   = w & 1;
    const int grp  = lane >> 2;
    const int tig  = lane & 3;

    float acc[2][4][4];
    mma_mainloop(Xs, Bfrag0, acc, mw, nw, grp, tig, lane);

    // epilogue 1: tanh(acc*gate) -> gmem + keep in regs
    float2 ov[2][2][4];   // [mt][half(r0/r1)][nt]
    #pragma unroll
    for (int mt = 0; mt < 2; mt++) {
        const int r0 = row0 + mw * 32 + mt * 16 + grp;
        const int r1 = r0 + 8;
        #pragma unroll
        for (int nt = 0; nt < 4; nt++) {
            const int c = nw * 32 + nt * 8 + tig * 2;
            float2 o0 = make_float2(0.f, 0.f), o1 = make_float2(0.f, 0.f);
            if (r0 < M) {
                float2 g = *(const float2*)&gate[r0 * 64 + c];
                o0.x = tanhf(acc[mt][nt][0] * g.x);
                o0.y = tanhf(acc[mt][nt][1] * g.y);
                *(float2*)&out_node[r0 * 64 + c] = o0;
            }
            if (r1 < M) {
                float2 g = *(const float2*)&gate[r1 * 64 + c];
                o1.x = tanhf(acc[mt][nt][2] * g.x);
                o1.y = tanhf(acc[mt][nt][3] * g.y);
                *(float2*)&out_node[r1 * 64 + c] = o1;
            }
            ov[mt][0][nt] = o0;
            ov[mt][1][nt] = o1;
        }
    }

    __syncthreads();   // everyone done reading Xs (pass 1)

    // write new_node tile into Xs (OOB rows stay zero: writes guarded)
    #pragma unroll
    for (int mt = 0; mt < 2; mt++) {
        const int rl0 = mw * 32 + mt * 16 + grp;
        const int rl1 = rl0 + 8;
        #pragma unroll
        for (int nt = 0; nt < 4; nt++) {
            const int c = nw * 32 + nt * 8 + tig * 2;
            if (row0 + rl0 < M) { Xs[rl0 * 68 + c] = ov[mt][0][nt].x; Xs[rl0 * 68 + c + 1] = ov[mt][0][nt].y; }
            if (row0 + rl1 < M) { Xs[rl1 * 68 + c] = ov[mt][1][nt].x; Xs[rl1 * 68 + c + 1] = ov[mt][1][nt].y; }
        }
    }
    __syncthreads();

    // pass 2: node_proj = new_node @ W_hn
    mma_mainloop(Xs, Bfrag1, acc, mw, nw, grp, tig, lane);
    #pragma unroll
    for (int mt = 0; mt < 2; mt++) {
        const int r0 = row0 + mw * 32 + mt * 16 + grp;
        const int r1 = r0 + 8;
        #pragma unroll
        for (int nt = 0; nt < 4; nt++) {
            const int c = nw * 32 + nt * 8 + tig * 2;
            if (r0 < M) *(float2*)&node_proj[r0 * 64 + c] = make_float2(acc[mt][nt][0], acc[mt][nt][1]);
            if (r1 < M) *(float2*)&node_proj[r1 * 64 + c] = make_float2(acc[mt][nt][2], acc[mt][nt][3]);
        }
    }
}

// ---------------- fused hedge kernel (steps 5+6) -----------------------------
// gate (smem) = CSR gather of node_proj rows; out = tanh((hedge_f @ W_hh) * gate)
__global__ __launch_bounds__(256, 2)
void fused_hedge_kernel(const float* __restrict__ X, const float* __restrict__ W,
                        const float* __restrict__ src, float* __restrict__ out,
                        int M, int seg_base)
{
    __shared__ float  Xs[128 * 68];
    __shared__ float4 Bfrag[8 * 8 * 32];
    __shared__ float  Gs[128 * 68];

    const int t    = threadIdx.x;
    const int row0 = blockIdx.x * 128;

    build_bfrag(W, Bfrag, t);
    stage_x(X, Xs, row0, M, t);

    // gather gate for this block's 128 rows: 16 lanes/row, 16 rows in flight
    {
        const int j = t & 15;
        const float4* src4 = (const float4*)src;
        #pragma unroll
        for (int rr = 0; rr < 8; rr++) {
            int sl = rr * 16 + (t >> 4);     // 0..127
            int s  = row0 + sl;
            if (s < M) {
                int beg = __ldg(&g_off[seg_base + s]);
                int end = __ldg(&g_off[seg_base + s + 1]);
                float4 a1 = make_float4(0.f, 0.f, 0.f, 0.f);
                float4 a2 = make_float4(0.f, 0.f, 0.f, 0.f);
                int i = beg;
                for (; i + 3 < end; i += 4) {
                    int r0 = __ldg(&g_ord[i]);
                    int r1 = __ldg(&g_ord[i + 1]);
                    int r2 = __ldg(&g_ord[i + 2]);
                    int r3 = __ldg(&g_ord[i + 3]);
                    float4 va = src4[r0 * 16 + j];
                    float4 vb = src4[r1 * 16 + j];
                    float4 vc = src4[r2 * 16 + j];
                    float4 vd = src4[r3 * 16 + j];
                    a1.x += va.x + vb.x; a1.y += va.y + vb.y;
                    a1.z += va.z + vb.z; a1.w += va.w + vb.w;
                    a2.x += vc.x + vd.x; a2.y += vc.y + vd.y;
                    a2.z += vc.z + vd.z; a2.w += vc.w + vd.w;
                }
                for (; i < end; i++) {
                    int r0 = __ldg(&g_ord[i]);
                    float4 va = src4[r0 * 16 + j];
                    a1.x += va.x; a1.y += va.y; a1.z += va.z; a1.w += va.w;
                }
                float* p = &Gs[sl * 68 + j * 4];
                p[0] = a1.x + a2.x; p[1] = a1.y + a2.y;
                p[2] = a1.z + a2.z; p[3] = a1.w + a2.w;
            }
        }
    }
    __syncthreads();

    const int lane = t & 31;
    const int w    = t >> 5;
    const int mw   = w >> 1;
    const int nw   = w & 1;
    const int grp  = lane >> 2;
    const int tig  = lane & 3;

    float acc[2][4][4];
    mma_mainloop(Xs, Bfrag, acc, mw, nw, grp, tig, lane);

    #pragma unroll
    for (int mt = 0; mt < 2; mt++) {
        const int rl0 = mw * 32 + mt * 16 + grp;
        const int rl1 = rl0 + 8;
        const int r0 = row0 + rl0;
        const int r1 = row0 + rl1;
        #pragma unroll
        for (int nt = 0; nt < 4; nt++) {
            const int c = nw * 32 + nt * 8 + tig * 2;
            if (r0 < M) {
                float2 o;
                o.x = tanhf(acc[mt][nt][0] * Gs[rl0 * 68 + c]);
                o.y = tanhf(acc[mt][nt][1] * Gs[rl0 * 68 + c + 1]);
                *(float2*)&out[r0 * 64 + c] = o;
            }
            if (r1 < M) {
                float2 o;
                o.x = tanhf(acc[mt][nt][2] * Gs[rl1 * 68 + c]);
                o.y = tanhf(acc[mt][nt][3] * Gs[rl1 * 68 + c + 1]);
                *(float2*)&out[r1 * 64 + c] = o;
            }
        }
    }
}

// ---------------- CSR build ---------------------------------------------------
__global__ __launch_bounds__(256)
void hist_kernel(const int* __restrict__ node_idx, const int* __restrict__ hedge_idx)
{
    int i = blockIdx.x * 256 + threadIdx.x;
    if (i < N_INC) {
        atomicAdd(&g_hist[__ldg(&node_idx[i])], 1);
        atomicAdd(&g_hist[N_NODES + __ldg(&hedge_idx[i])], 1);
    }
}

__global__ __launch_bounds__(1024)
void scan1_kernel()
{
    __shared__ int sh[1024];
    int b = blockIdx.x, t = threadIdx.x;
    int base = b * 4096 + t * 4;
    int v[4]; int s = 0;
    #pragma unroll
    for (int j = 0; j < 4; j++) {
        int x = (base + j < N_SEG) ? g_hist[base + j] : 0;
        v[j] = s; s += x;
    }
    sh[t] = s; __syncthreads();
    for (int ofs = 1; ofs < 1024; ofs <<= 1) {
        int x = 0;
        if (t >= ofs) x = sh[t - ofs];
        __syncthreads();
        if (t >= ofs) sh[t] += x;
        __syncthreads();
    }
    int excl = sh[t] - s;
    if (t == 1023) g_blocksums[b] = sh[t];
    #pragma unroll
    for (int j = 0; j < 4; j++)
        if (base + j < N_SEG) g_off[base + j] = excl + v[j];
}

__global__ __launch_bounds__(128)
void scan2_kernel()
{
    __shared__ int sh[128];
    int t = threadIdx.x;
    int s = (t < SCAN_BLOCKS) ? g_blocksums[t] : 0;
    sh[t] = s; __syncthreads();
    for (int ofs = 1; ofs < 128; ofs <<= 1) {
        int x = 0;
        if (t >= ofs) x = sh[t - ofs];
        __syncthreads();
        if (t >= ofs) sh[t] += x;
        __syncthreads();
    }
    g_blocksums[t] = sh[t] - s;
    if (t == 0) g_off[N_SEG] = 2 * N_INC;
}

__global__ __launch_bounds__(1024)
void scan3_kernel()
{
    int b = blockIdx.x, t = threadIdx.x;
    int add = g_blocksums[b];
    int base = b * 4096;
    #pragma unroll
    for (int j = 0; j < 4; j++) {
        int i = base + t + j * 1024;
        if (i < N_SEG) g_off[i] += add;
    }
}

__global__ __launch_bounds__(256)
void reorder_kernel(const int* __restrict__ node_idx, const int* __restrict__ hedge_idx)
{
    int i = blockIdx.x * 256 + threadIdx.x;
    if (i < N_INC) {
        int n = __ldg(&node_idx[i]);
        int h = __ldg(&hedge_idx[i]);
        int pn = atomicAdd(&g_hist[n], 1);
        g_ord[g_off[n] + pn] = h;
        int ph = atomicAdd(&g_hist[N_NODES + h], 1);
        g_ord[g_off[N_NODES + h] + ph] = n;
    }
}

// ---------------- standalone node gather (step 2) ----------------------------
__global__ __launch_bounds__(256)
void gather_kernel(const float* __restrict__ src, float* __restrict__ dst,
                   int seg_base, int n_seg)
{
    int s = blockIdx.x * 16 + (threadIdx.x >> 4);
    int j = threadIdx.x & 15;
    if (s >= n_seg) return;
    int beg = __ldg(&g_off[seg_base + s]);
    int end = __ldg(&g_off[seg_base + s + 1]);
    const float4* src4 = (const float4*)src;
    float4 a1 = make_float4(0.f, 0.f, 0.f, 0.f);
    float4 a2 = make_float4(0.f, 0.f, 0.f, 0.f);
    int i = beg;
    for (; i + 3 < end; i += 4) {
        int r0 = __ldg(&g_ord[i]);
        int r1 = __ldg(&g_ord[i + 1]);
        int r2 = __ldg(&g_ord[i + 2]);
        int r3 = __ldg(&g_ord[i + 3]);
        float4 va = src4[r0 * 16 + j];
        float4 vb = src4[r1 * 16 + j];
        float4 vc = src4[r2 * 16 + j];
        float4 vd = src4[r3 * 16 + j];
        a1.x += va.x + vb.x; a1.y += va.y + vb.y;
        a1.z += va.z + vb.z; a1.w += va.w + vb.w;
        a2.x += vc.x + vd.x; a2.y += vc.y + vd.y;
        a2.z += vc.z + vd.z; a2.w += vc.w + vd.w;
    }
    for (; i < end; i++) {
        int r0 = __ldg(&g_ord[i]);
        float4 va = src4[r0 * 16 + j];
        a1.x += va.x; a1.y += va.y; a1.z += va.z; a1.w += va.w;
    }
    float4 o = make_float4(a1.x + a2.x, a1.y + a2.y, a1.z + a2.z, a1.w + a2.w);
    ((float4*)dst)[s * 16 + j] = o;
}

// ---------------- launch ------------------------------------------------------
extern "C" void kernel_launch(void* const* d_in, const int* in_sizes, int n_in,
                              void* d_out, int out_size)
{
    const float* node_f    = (const float*)d_in[0];
    const float* hedge_f   = (const float*)d_in[1];
    const float* W_nn      = (const float*)d_in[2];
    const float* W_nh      = (const float*)d_in[3];
    const float* W_hh      = (const float*)d_in[4];
    const float* W_hn      = (const float*)d_in[5];
    const int*   node_idx  = (const int*)d_in[6];
    const int*   hedge_idx = (const int*)d_in[7];

    float* out_node  = (float*)d_out;                       // [N_NODES, 64]
    float* out_hedge = out_node + (size_t)N_NODES * D;      // [N_HEDGES, 64]

    float *hp, *np, *gn;
    int   *hist;
    cudaGetSymbolAddress((void**)&hp,   g_hedge_proj);
    cudaGetSymbolAddress((void**)&np,   g_node_proj);
    cudaGetSymbolAddress((void**)&gn,   g_gate_node);
    cudaGetSymbolAddress((void**)&hist, g_hist);

    const int grid_n   = (N_NODES  + 127) / 128;   // 1563
    const int grid_h   = (N_HEDGES + 127) / 128;   // 782
    const int grid_inc = (N_INC + 255) / 256;      // 6250
    const int grid_gn  = (N_NODES  + 15) / 16;     // 12500

    // ---- CSR build
    cudaMemsetAsync(hist, 0, N_SEG * sizeof(int), 0);
    hist_kernel<<<grid_inc, 256>>>(node_idx, hedge_idx);
    scan1_kernel<<<SCAN_BLOCKS, 1024>>>();
    scan2_kernel<<<1, 128>>>();
    scan3_kernel<<<SCAN_BLOCKS, 1024>>>();
    cudaMemsetAsync(hist, 0, N_SEG * sizeof(int), 0);
    reorder_kernel<<<grid_inc, 256>>>(node_idx, hedge_idx);

    // ---- pipeline
    // 1) hedge_proj = hedge_features @ W_nh
    proj_mma_kernel<<<grid_h, 256>>>(hedge_f, W_nh, hp, N_HEDGES);
    // 2) gate_node[n] = sum_{h in adj(n)} hedge_proj[h]
    gather_kernel<<<grid_gn, 256>>>(hp, gn, 0, N_NODES);
    // 3+4) new_node = tanh((node_f@W_nn)*gate_node); node_proj = new_node@W_hn
    fused_node_kernel<<<grid_n, 256>>>(node_f, W_nn, W_hn, gn, out_node, np, N_NODES);
    // 5+6) gate_hedge gather (smem) + out_hedge = tanh((hedge_f@W_hh)*gate)
    fused_hedge_kernel<<<grid_h, 256>>>(hedge_f, W_hh, np, out_hedge, N_HEDGES, N_NODES);
}

// round 16
// speedup vs baseline: 1.1840x; 1.1840x over previous
#include <cuda_runtime.h>
#include <math.h>

#define N_NODES  200000
#define N_HEDGES 100000
#define N_INC    1600000
#define D        64
#define N_SEG    (N_NODES + N_HEDGES)       // 300000
#define SCAN_BLOCKS 74                       // ceil(300000 / 4096)

// ---------------- scratch (static device globals; no allocation) ------------
__device__ float g_hedge_proj[N_HEDGES * D];   // hedge_features @ W_nh
__device__ float g_node_proj [N_NODES  * D];   // new_node @ W_hn
__device__ float g_gate_node [N_NODES  * D];   // segment_sum -> nodes
__device__ float g_gate_hedge[N_HEDGES * D];   // segment_sum -> hedges
__device__ int   g_hist[N_SEG];                // degree counts (scan input)
__device__ int   g_off [N_SEG + 1];            // CSR offsets; post-reorder = seg END
__device__ int   g_ord [2 * N_INC];            // CSR adjacency (source row ids)
__device__ int   g_scan_status[SCAN_BLOCKS];   // 0 pending / 1 agg / 2 prefix
__device__ int   g_scan_agg   [SCAN_BLOCKS];
__device__ int   g_scan_pref  [SCAN_BLOCKS];

// ---------------- helpers ----------------------------------------------------
__device__ __forceinline__ unsigned tf_hi(float f) {
    unsigned r;
    asm("cvt.rna.tf32.f32 %0, %1;" : "=r"(r) : "f"(f));
    return r;
}

__device__ __forceinline__ void mma_tf32(float* c,
                                         unsigned a0, unsigned a1, unsigned a2, unsigned a3,
                                         unsigned b0, unsigned b1)
{
    asm volatile(
        "mma.sync.aligned.m16n8k8.row.col.f32.tf32.tf32.f32 "
        "{%0,%1,%2,%3}, {%4,%5,%6,%7}, {%8,%9}, {%0,%1,%2,%3};"
        : "+f"(c[0]), "+f"(c[1]), "+f"(c[2]), "+f"(c[3])
        : "r"(a0), "r"(a1), "r"(a2), "r"(a3), "r"(b0), "r"(b1));
}

// ---------------- 3xTF32 tensor-core GEMM (validated R12/R13 version) --------
// out[r][c] = X[r][:] @ W[:][c]               (MODE==0)
// out[r][c] = tanhf((X@W)[r][c] * gate[r][c]) (MODE==1)
template <int MODE>
__global__ __launch_bounds__(256)
void proj_mma_kernel(const float* __restrict__ X, const float* __restrict__ W,
                     const float* __restrict__ gate, float* __restrict__ out, int M)
{
    __shared__ float  Xs[128 * 68];
    __shared__ float4 Bfrag[8 * 8 * 32];

    const int t    = threadIdx.x;
    const int row0 = blockIdx.x * 128;

    {
        const int lane = t & 31;
        const int kk   = t >> 5;
        const int grp  = lane >> 2;
        const int tig  = lane & 3;
        const int base = (kk * 8 + tig) * 64 + grp;
        #pragma unroll
        for (int nt = 0; nt < 8; nt++) {
            float v0 = __ldg(&W[base + nt * 8]);
            float v1 = __ldg(&W[base + 4 * 64 + nt * 8]);
            float h0 = __uint_as_float(tf_hi(v0));
            float h1 = __uint_as_float(tf_hi(v1));
            float l0 = __uint_as_float(tf_hi(v0 - h0));
            float l1 = __uint_as_float(tf_hi(v1 - h1));
            Bfrag[(nt * 8 + kk) * 32 + lane] = make_float4(h0, h1, l0, l1);
        }
    }
    {
        const float4* X4 = (const float4*)X;
        #pragma unroll
        for (int jj = 0; jj < 8; jj++) {
            int i4  = t + jj * 256;
            int r   = i4 >> 4;
            int kq  = i4 & 15;
            int row = row0 + r;
            float4 v = make_float4(0.f, 0.f, 0.f, 0.f);
            if (row < M) v = X4[row * 16 + kq];
            float* p = &Xs[r * 68 + kq * 4];
            p[0] = v.x; p[1] = v.y; p[2] = v.z; p[3] = v.w;
        }
    }
    __syncthreads();

    const int lane = t & 31;
    const int w    = t >> 5;
    const int mw   = w >> 1;
    const int nw   = w & 1;
    const int grp  = lane >> 2;
    const int tig  = lane & 3;

    float acc[2][4][4];
    #pragma unroll
    for (int mt = 0; mt < 2; mt++)
        #pragma unroll
        for (int nt = 0; nt < 4; nt++)
            #pragma unroll
            for (int j = 0; j < 4; j++) acc[mt][nt][j] = 0.f;

    const float* xr00 = &Xs[(mw * 32 +      grp) * 68];
    const float* xr01 = &Xs[(mw * 32 +  8 + grp) * 68];
    const float* xr10 = &Xs[(mw * 32 + 16 + grp) * 68];
    const float* xr11 = &Xs[(mw * 32 + 24 + grp) * 68];

    #pragma unroll
    for (int kk = 0; kk < 8; kk++) {
        const int kb = kk * 8;
        unsigned ah[2][4], al[2][4];
        {
            float x0, x1, x2, x3;
            x0 = xr00[kb + tig]; x1 = xr01[kb + tig];
            x2 = xr00[kb + tig + 4]; x3 = xr01[kb + tig + 4];
            ah[0][0] = tf_hi(x0); al[0][0] = tf_hi(x0 - __uint_as_float(ah[0][0]));
            ah[0][1] = tf_hi(x1); al[0][1] = tf_hi(x1 - __uint_as_float(ah[0][1]));
            ah[0][2] = tf_hi(x2); al[0][2] = tf_hi(x2 - __uint_as_float(ah[0][2]));
            ah[0][3] = tf_hi(x3); al[0][3] = tf_hi(x3 - __uint_as_float(ah[0][3]));
            x0 = xr10[kb + tig]; x1 = xr11[kb + tig];
            x2 = xr10[kb + tig + 4]; x3 = xr11[kb + tig + 4];
            ah[1][0] = tf_hi(x0); al[1][0] = tf_hi(x0 - __uint_as_float(ah[1][0]));
            ah[1][1] = tf_hi(x1); al[1][1] = tf_hi(x1 - __uint_as_float(ah[1][1]));
            ah[1][2] = tf_hi(x2); al[1][2] = tf_hi(x2 - __uint_as_float(ah[1][2]));
            ah[1][3] = tf_hi(x3); al[1][3] = tf_hi(x3 - __uint_as_float(ah[1][3]));
        }
        #pragma unroll
        for (int nt = 0; nt < 4; nt++) {
            float4 b = Bfrag[((nw * 4 + nt) * 8 + kk) * 32 + lane];
            unsigned bh0 = __float_as_uint(b.x);
            unsigned bh1 = __float_as_uint(b.y);
            unsigned bl0 = __float_as_uint(b.z);
            unsigned bl1 = __float_as_uint(b.w);
            #pragma unroll
            for (int mt = 0; mt < 2; mt++) {
                mma_tf32(acc[mt][nt], ah[mt][0], ah[mt][1], ah[mt][2], ah[mt][3], bh0, bh1);
                mma_tf32(acc[mt][nt], al[mt][0], al[mt][1], al[mt][2], al[mt][3], bh0, bh1);
                mma_tf32(acc[mt][nt], ah[mt][0], ah[mt][1], ah[mt][2], ah[mt][3], bl0, bl1);
            }
        }
    }

    #pragma unroll
    for (int mt = 0; mt < 2; mt++) {
        const int r0 = row0 + mw * 32 + mt * 16 + grp;
        const int r1 = r0 + 8;
        #pragma unroll
        for (int nt = 0; nt < 4; nt++) {
            const int c = nw * 32 + nt * 8 + tig * 2;
            if (r0 < M) {
                float2 o;
                if (MODE == 1) {
                    float2 g = *(const float2*)&gate[r0 * 64 + c];
                    o.x = tanhf(acc[mt][nt][0] * g.x);
                    o.y = tanhf(acc[mt][nt][1] * g.y);
                } else {
                    o.x = acc[mt][nt][0]; o.y = acc[mt][nt][1];
                }
                *(float2*)&out[r0 * 64 + c] = o;
            }
            if (r1 < M) {
                float2 o;
                if (MODE == 1) {
                    float2 g = *(const float2*)&gate[r1 * 64 + c];
                    o.x = tanhf(acc[mt][nt][2] * g.x);
                    o.y = tanhf(acc[mt][nt][3] * g.y);
                } else {
                    o.x = acc[mt][nt][2]; o.y = acc[mt][nt][3];
                }
                *(float2*)&out[r1 * 64 + c] = o;
            }
        }
    }
}

// ---------------- CSR build ---------------------------------------------------
__global__ __launch_bounds__(256)
void hist_kernel(const int* __restrict__ node_idx, const int* __restrict__ hedge_idx)
{
    int i = blockIdx.x * 256 + threadIdx.x;
    if (i < N_INC) {
        atomicAdd(&g_hist[__ldg(&node_idx[i])], 1);
        atomicAdd(&g_hist[N_NODES + __ldg(&hedge_idx[i])], 1);
    }
}

// Single-pass exclusive scan via decoupled lookback. 74 blocks, all resident
// on 148 SMs -> spin-wait is deadlock-free. Writes exclusive prefix to g_off.
__global__ __launch_bounds__(1024)
void scan_lookback_kernel()
{
    __shared__ int sh[1024];
    __shared__ int sh_excl;
    const int b = blockIdx.x, t = threadIdx.x;
    const int base = b * 4096 + t * 4;

    int v[4]; int s = 0;
    #pragma unroll
    for (int j = 0; j < 4; j++) {
        int x = (base + j < N_SEG) ? g_hist[base + j] : 0;
        v[j] = s; s += x;
    }
    sh[t] = s; __syncthreads();
    for (int ofs = 1; ofs < 1024; ofs <<= 1) {
        int x = 0;
        if (t >= ofs) x = sh[t - ofs];
        __syncthreads();
        if (t >= ofs) sh[t] += x;
        __syncthreads();
    }
    const int block_incl = sh[t];
    const int agg = sh[1023];

    if (t == 0) {
        if (b == 0) {
            g_scan_pref[0] = agg;
            __threadfence();
            atomicExch(&g_scan_status[0], 2);
            sh_excl = 0;
        } else {
            g_scan_agg[b] = agg;
            __threadfence();
            atomicExch(&g_scan_status[b], 1);
            int run = 0;
            for (int i = b - 1; ; ) {
                int st;
                do { st = atomicAdd(&g_scan_status[i], 0); } while (st == 0);
                if (st == 2) { run += atomicAdd(&g_scan_pref[i], 0); break; }
                run += atomicAdd(&g_scan_agg[i], 0);
                i--;
            }
            g_scan_pref[b] = run + agg;
            __threadfence();
            atomicExch(&g_scan_status[b], 2);
            sh_excl = run;
        }
    }
    __syncthreads();

    const int excl = sh_excl + block_incl - s;
    #pragma unroll
    for (int j = 0; j < 4; j++)
        if (base + j < N_SEG) g_off[base + j] = excl + v[j];
}

// Fill adjacency, bumping g_off[seg] directly as the cursor. Post-kernel,
// g_off[seg] holds the segment's END offset (= original exclusive prefix of
// seg+1), so consumers use: beg = (seg==0) ? 0 : g_off[seg-1], end = g_off[seg].
__global__ __launch_bounds__(256)
void reorder_kernel(const int* __restrict__ node_idx, const int* __restrict__ hedge_idx)
{
    int i = blockIdx.x * 256 + threadIdx.x;
    if (i < N_INC) {
        int n = __ldg(&node_idx[i]);
        int h = __ldg(&hedge_idx[i]);
        int pn = atomicAdd(&g_off[n], 1);
        g_ord[pn] = h;
        int ph = atomicAdd(&g_off[N_NODES + h], 1);
        g_ord[ph] = n;
    }
}

// ---------------- CSR segment-sum gather (shifted-offset convention) ---------
__global__ __launch_bounds__(256)
void gather_kernel(const float* __restrict__ src, float* __restrict__ dst,
                   int seg_base, int n_seg)
{
    int s = blockIdx.x * 16 + (threadIdx.x >> 4);
    int j = threadIdx.x & 15;
    if (s >= n_seg) return;
    int gs  = seg_base + s;
    int end = __ldg(&g_off[gs]);
    int beg = (gs == 0) ? 0 : __ldg(&g_off[gs - 1]);
    const float4* src4 = (const float4*)src;
    float4 a1 = make_float4(0.f, 0.f, 0.f, 0.f);
    float4 a2 = make_float4(0.f, 0.f, 0.f, 0.f);
    int i = beg;
    for (; i + 3 < end; i += 4) {
        int r0 = __ldg(&g_ord[i]);
        int r1 = __ldg(&g_ord[i + 1]);
        int r2 = __ldg(&g_ord[i + 2]);
        int r3 = __ldg(&g_ord[i + 3]);
        float4 va = src4[r0 * 16 + j];
        float4 vb = src4[r1 * 16 + j];
        float4 vc = src4[r2 * 16 + j];
        float4 vd = src4[r3 * 16 + j];
        a1.x += va.x + vb.x; a1.y += va.y + vb.y;
        a1.z += va.z + vb.z; a1.w += va.w + vb.w;
        a2.x += vc.x + vd.x; a2.y += vc.y + vd.y;
        a2.z += vc.z + vd.z; a2.w += vc.w + vd.w;
    }
    for (; i < end; i++) {
        int r0 = __ldg(&g_ord[i]);
        float4 va = src4[r0 * 16 + j];
        a1.x += va.x; a1.y += va.y; a1.z += va.z; a1.w += va.w;
    }
    float4 o = make_float4(a1.x + a2.x, a1.y + a2.y, a1.z + a2.z, a1.w + a2.w);
    ((float4*)dst)[s * 16 + j] = o;
}

// ---------------- launch ------------------------------------------------------
extern "C" void kernel_launch(void* const* d_in, const int* in_sizes, int n_in,
                              void* d_out, int out_size)
{
    const float* node_f    = (const float*)d_in[0];
    const float* hedge_f   = (const float*)d_in[1];
    const float* W_nn      = (const float*)d_in[2];
    const float* W_nh      = (const float*)d_in[3];
    const float* W_hh      = (const float*)d_in[4];
    const float* W_hn      = (const float*)d_in[5];
    const int*   node_idx  = (const int*)d_in[6];
    const int*   hedge_idx = (const int*)d_in[7];

    float* out_node  = (float*)d_out;                       // [N_NODES, 64]
    float* out_hedge = out_node + (size_t)N_NODES * D;      // [N_HEDGES, 64]

    float *hp, *np, *gn, *gh;
    int   *hist, *status;
    cudaGetSymbolAddress((void**)&hp,     g_hedge_proj);
    cudaGetSymbolAddress((void**)&np,     g_node_proj);
    cudaGetSymbolAddress((void**)&gn,     g_gate_node);
    cudaGetSymbolAddress((void**)&gh,     g_gate_hedge);
    cudaGetSymbolAddress((void**)&hist,   g_hist);
    cudaGetSymbolAddress((void**)&status, g_scan_status);

    // side stream + fork/join events (created once, on the first -- uncaptured --
    // call; reused by the capture call; identical launched work every call)
    static cudaStream_t s1 = []() {
        cudaStream_t s; cudaStreamCreateWithFlags(&s, cudaStreamNonBlocking); return s;
    }();
    static cudaEvent_t evF = []() {
        cudaEvent_t e; cudaEventCreateWithFlags(&e, cudaEventDisableTiming); return e;
    }();
    static cudaEvent_t evJ = []() {
        cudaEvent_t e; cudaEventCreateWithFlags(&e, cudaEventDisableTiming); return e;
    }();

    const int grid_n   = (N_NODES  + 127) / 128;   // 1563
    const int grid_h   = (N_HEDGES + 127) / 128;   // 782
    const int grid_inc = (N_INC + 255) / 256;      // 6250
    const int grid_gn  = (N_NODES  + 15) / 16;     // 12500
    const int grid_gh  = (N_HEDGES + 15) / 16;     // 6250

    // ---- fork: CSR build on s1, first GEMM on stream 0 ----------------------
    cudaEventRecord(evF, 0);
    cudaStreamWaitEvent(s1, evF, 0);
    cudaMemsetAsync(hist,   0, N_SEG * sizeof(int),       s1);
    cudaMemsetAsync(status, 0, SCAN_BLOCKS * sizeof(int), s1);
    hist_kernel<<<grid_inc, 256, 0, s1>>>(node_idx, hedge_idx);
    scan_lookback_kernel<<<SCAN_BLOCKS, 1024, 0, s1>>>();
    reorder_kernel<<<grid_inc, 256, 0, s1>>>(node_idx, hedge_idx);
    cudaEventRecord(evJ, s1);

    // 1) hedge_proj = hedge_features @ W_nh   (independent of CSR)
    proj_mma_kernel<0><<<grid_h, 256>>>(hedge_f, W_nh, nullptr, hp, N_HEDGES);

    // ---- join ---------------------------------------------------------------
    cudaStreamWaitEvent(0, evJ, 0);

    // 2) gate_node[n] = sum_{h in adj(n)} hedge_proj[h]
    gather_kernel<<<grid_gn, 256>>>(hp, gn, 0, N_NODES);
    // 3) new_node = tanh((node_features @ W_nn) * gate_node)
    proj_mma_kernel<1><<<grid_n, 256>>>(node_f, W_nn, gn, out_node, N_NODES);
    // 4) node_proj = new_node @ W_hn
    proj_mma_kernel<0><<<grid_n, 256>>>(out_node, W_hn, nullptr, np, N_NODES);
    // 5) gate_hedge[h] = sum_{n in adj(h)} node_proj[n]
    gather_kernel<<<grid_gh, 256>>>(np, gh, N_NODES, N_HEDGES);
    // 6) new_hedge = tanh((hedge_features @ W_hh) * gate_hedge)
    proj_mma_kernel<1><<<grid_h, 256>>>(hedge_f, W_hh, gh, out_hedge, N_HEDGES);
}